// round 5
// baseline (speedup 1.0000x reference)
#include <cuda_runtime.h>
#include <cstdint>

#define BB 4
#define SEQ 2048
#define EMB 1024
#define NH 16
#define HD 64
#define MT (BB * SEQ)  // 8192 tokens

// Scratch (allocation-free rule: device globals)
__device__ float g_q[BB * NH * SEQ * HD];   // [b][h][s][d]
__device__ float g_k[BB * NH * SEQ * HD];
__device__ float g_v[BB * NH * SEQ * HD];
__device__ float g_ao[MT * EMB];            // attention out, [b][s][h*64+d] == [m][e]

// ---------------------------------------------------------------------------
// tf32 helpers (baseline PTX, works at .target sm_100)
// ---------------------------------------------------------------------------
__device__ __forceinline__ uint32_t f2tf32(float x) {
  uint32_t r;
  asm("cvt.rna.tf32.f32 %0, %1;" : "=r"(r) : "f"(x));
  return r;
}

__device__ __forceinline__ void split1(float v, uint32_t& h, uint32_t& l) {
  h = f2tf32(v);
  l = f2tf32(v - __uint_as_float(h));
}

__device__ __forceinline__ void mma_tf32(float* c, const uint32_t* a,
                                         const uint32_t* b) {
  asm volatile(
      "mma.sync.aligned.m16n8k8.row.col.f32.tf32.tf32.f32 "
      "{%0,%1,%2,%3}, {%4,%5,%6,%7}, {%8,%9}, {%0,%1,%2,%3};"
      : "+f"(c[0]), "+f"(c[1]), "+f"(c[2]), "+f"(c[3])
      : "r"(a[0]), "r"(a[1]), "r"(a[2]), "r"(a[3]), "r"(b[0]), "r"(b[1]));
}

// ---------------------------------------------------------------------------
// tf32 3x-split GEMM via mma.sync: D[m][n] = sum_k A[m][k]*B[n][k] + bias[n]
// CTA 128x128, BK=16, 256 threads (8 warps, each 64x32 out).
// MODE 0: A=query, scatter into g_q/g_k/g_v. MODE 1: A=g_ao, write out.
// ---------------------------------------------------------------------------
#define SPAD 20  // row stride in words for 16-col tile (conflict-free frags)

template <int MODE>
__global__ __launch_bounds__(256) void gemm_mma_kernel(
    const float* __restrict__ A, const float* __restrict__ B,
    const float* __restrict__ bias, float* __restrict__ out) {
  __shared__ uint32_t s_ahi[128 * SPAD];
  __shared__ uint32_t s_alo[128 * SPAD];
  __shared__ uint32_t s_bhi[128 * SPAD];
  __shared__ uint32_t s_blo[128 * SPAD];

  const int tid = threadIdx.x;
  const int lane = tid & 31;
  const int wid = tid >> 5;
  const int warp_m = wid & 1;        // 2 warps over M
  const int warp_n = wid >> 1;       // 4 warps over N
  const int m0 = blockIdx.y * 128;
  const int n0 = blockIdx.x * 128;

  const float* Asrc = (MODE == 0) ? A : g_ao;

  const int ldr = tid >> 2;          // rows 0..63 (+64 for second half)
  const int ldc = (tid & 3) * 4;     // 0,4,8,12

  const float* Ap0 = Asrc + (size_t)(m0 + ldr) * EMB + ldc;
  const float* Ap1 = Asrc + (size_t)(m0 + 64 + ldr) * EMB + ldc;
  const float* Bp0 = B + (size_t)(n0 + ldr) * EMB + ldc;
  const float* Bp1 = B + (size_t)(n0 + 64 + ldr) * EMB + ldc;

  float acc[4][4][4] = {};  // [mt][nt][reg]

  float4 pa0, pa1, pb0, pb1;
  pa0 = *(const float4*)(Ap0);
  pa1 = *(const float4*)(Ap1);
  pb0 = *(const float4*)(Bp0);
  pb1 = *(const float4*)(Bp1);

  const int s0 = ldr * SPAD + ldc;
  const int s1 = (ldr + 64) * SPAD + ldc;

  for (int c = 0; c < EMB / 16; ++c) {
    if (c > 0) __syncthreads();

    {
      uint4 h, l;
      split1(pa0.x, h.x, l.x); split1(pa0.y, h.y, l.y);
      split1(pa0.z, h.z, l.z); split1(pa0.w, h.w, l.w);
      *(uint4*)&s_ahi[s0] = h; *(uint4*)&s_alo[s0] = l;
      split1(pa1.x, h.x, l.x); split1(pa1.y, h.y, l.y);
      split1(pa1.z, h.z, l.z); split1(pa1.w, h.w, l.w);
      *(uint4*)&s_ahi[s1] = h; *(uint4*)&s_alo[s1] = l;
      split1(pb0.x, h.x, l.x); split1(pb0.y, h.y, l.y);
      split1(pb0.z, h.z, l.z); split1(pb0.w, h.w, l.w);
      *(uint4*)&s_bhi[s0] = h; *(uint4*)&s_blo[s0] = l;
      split1(pb1.x, h.x, l.x); split1(pb1.y, h.y, l.y);
      split1(pb1.z, h.z, l.z); split1(pb1.w, h.w, l.w);
      *(uint4*)&s_bhi[s1] = h; *(uint4*)&s_blo[s1] = l;
    }
    __syncthreads();

    if (c + 1 < EMB / 16) {
      const int off = (c + 1) * 16;
      pa0 = *(const float4*)(Ap0 + off);
      pa1 = *(const float4*)(Ap1 + off);
      pb0 = *(const float4*)(Bp0 + off);
      pb1 = *(const float4*)(Bp1 + off);
    }

#pragma unroll
    for (int kc = 0; kc < 2; ++kc) {
      const int kb = kc * 8 + (lane & 3);
      uint32_t ah[4][4], al[4][4];
#pragma unroll
      for (int mt = 0; mt < 4; ++mt) {
        const int r = warp_m * 64 + mt * 16 + (lane >> 2);
        const int i0 = r * SPAD + kb;
        const int i1 = (r + 8) * SPAD + kb;
        ah[mt][0] = s_ahi[i0];     ah[mt][1] = s_ahi[i1];
        ah[mt][2] = s_ahi[i0 + 4]; ah[mt][3] = s_ahi[i1 + 4];
        al[mt][0] = s_alo[i0];     al[mt][1] = s_alo[i1];
        al[mt][2] = s_alo[i0 + 4]; al[mt][3] = s_alo[i1 + 4];
      }
      uint32_t bh[4][2], bl[4][2];
#pragma unroll
      for (int nt = 0; nt < 4; ++nt) {
        const int n = warp_n * 32 + nt * 8 + (lane >> 2);
        const int i0 = n * SPAD + kb;
        bh[nt][0] = s_bhi[i0]; bh[nt][1] = s_bhi[i0 + 4];
        bl[nt][0] = s_blo[i0]; bl[nt][1] = s_blo[i0 + 4];
      }
#pragma unroll
      for (int mt = 0; mt < 4; ++mt)
#pragma unroll
        for (int nt = 0; nt < 4; ++nt) {
          mma_tf32(acc[mt][nt], ah[mt], bh[nt]);
          mma_tf32(acc[mt][nt], ah[mt], bl[nt]);
          mma_tf32(acc[mt][nt], al[mt], bh[nt]);
        }
    }
  }

#pragma unroll
  for (int mt = 0; mt < 4; ++mt) {
#pragma unroll
    for (int nt = 0; nt < 4; ++nt) {
      const int r = m0 + warp_m * 64 + mt * 16 + (lane >> 2);
      const int n = n0 + warp_n * 32 + nt * 8 + (lane & 3) * 2;
      const float b0 = bias[n], b1 = bias[n + 1];
      float2 v0 = {acc[mt][nt][0] + b0, acc[mt][nt][1] + b1};
      float2 v1 = {acc[mt][nt][2] + b0, acc[mt][nt][3] + b1};
      if (MODE == 0) {
        const int which = n >> 10;
        float* dstv = (which == 0) ? g_q : (which == 1) ? g_k : g_v;
        const int rem = n & 1023;
        const int h = rem >> 6;
        const int d = rem & 63;
        const int b_ = r >> 11, s_ = r & 2047;
        float* base = dstv + (size_t)(((b_ << 4) + h) * SEQ) * HD + d;
        *(float2*)(base + (size_t)s_ * HD) = v0;
        *(float2*)(base + (size_t)(s_ + 8) * HD) = v1;
      } else {
        *(float2*)(out + (size_t)r * EMB + n) = v0;
        *(float2*)(out + (size_t)(r + 8) * EMB + n) = v1;
      }
    }
  }
}

// ---------------------------------------------------------------------------
// Flash attention with mma.sync tf32 3x-split.
// CTA: 64 q-rows, 4 warps (warp w owns rows w*16..w*16+15). KV tiles of 32.
// K/V/P stored in smem as packed uint2 fragment pairs:
//   K2[key][ks*4+qp]  = (K[key][ks*8+qp],   K[key][ks*8+qp+4])
//   V2[d][kst*4+qp]   = (V[kst*8+qp][d],    V[kst*8+qp+4][d])
//   P2[row][kst*4+qp] = (P[row][kst*8+qp],  P[row][kst*8+qp+4])
// Row strides: K2=36 uint2 (72w), V2/P2=20 uint2 (40w) -> stride ≡ 8 (mod 32)
// words -> conflict-free LDS.64 fragment fetches.
// scores scaled by 1/sqrt(EMB) = 1/32.
// ---------------------------------------------------------------------------
struct AttnSmem {
  float Qs[64][68];        // staging for Q (17408 B)
  uint2 K2h[32][36];       // 9216 B
  uint2 K2l[32][36];
  uint2 V2h[64][20];       // 10240 B
  uint2 V2l[64][20];
  uint2 P2h[64][20];
  uint2 P2l[64][20];
};
#define ATTN_SMEM_BYTES sizeof(AttnSmem)

__global__ __launch_bounds__(128) void flash_mma_kernel() {
  extern __shared__ char dsm_raw[];
  AttnSmem* sm = reinterpret_cast<AttnSmem*>(dsm_raw);

  const int tid = threadIdx.x;
  const int lane = tid & 31;
  const int w = tid >> 5;
  const int grp = lane >> 2;     // 0..7
  const int qp = lane & 3;       // 0..3
  const int bh = blockIdx.x;     // 0..63
  const int q0 = blockIdx.y * 64;
  const int b = bh >> 4, h = bh & 15;
  const int qrow = w * 16 + grp;

  const float* Qg = g_q + (size_t)(bh * SEQ + q0) * HD;
  const float* Kg = g_k + (size_t)bh * SEQ * HD;
  const float* Vg = g_v + (size_t)bh * SEQ * HD;

  // ---- load Q tile (64x64) to smem, coalesced ----
#pragma unroll
  for (int it = 0; it < 8; ++it) {
    const int slot = it * 128 + tid;   // 0..1023 float4 slots
    const int r = slot >> 4;
    const int c = (slot & 15) * 4;
    *(float4*)&sm->Qs[r][c] = *(const float4*)(Qg + r * HD + c);
  }
  __syncthreads();

  // ---- extract per-thread Q fragments (held in regs for whole CTA) ----
  uint32_t qh[8][4], ql[8][4];
#pragma unroll
  for (int ks = 0; ks < 8; ++ks) {
    split1(sm->Qs[qrow][ks * 8 + qp],          qh[ks][0], ql[ks][0]);
    split1(sm->Qs[qrow + 8][ks * 8 + qp],      qh[ks][1], ql[ks][1]);
    split1(sm->Qs[qrow][ks * 8 + qp + 4],      qh[ks][2], ql[ks][2]);
    split1(sm->Qs[qrow + 8][ks * 8 + qp + 4],  qh[ks][3], ql[ks][3]);
  }

  float o[8][4] = {};                  // O accum [d-tile][reg]
  float m0v = -1e30f, m1v = -1e30f;    // row maxima (scaled domain)
  float l0v = 0.f, l1v = 0.f;
  const float SCALE = 0.03125f;        // 1/sqrt(1024)

  for (int j0 = 0; j0 < SEQ; j0 += 32) {
    __syncthreads();   // smem K/V consumed by previous iteration

    // ---- load + split K,V tile (32 keys x 64 d) into packed layouts ----
#pragma unroll
    for (int it = 0; it < 4; ++it) {
      const int slot = it * 128 + tid;  // 0..511 float4 slots
      const int key = slot >> 4;        // 0..31
      const int c4 = (slot & 15) * 4;   // 0..60
      const float4 kv = *(const float4*)(Kg + (size_t)(j0 + key) * HD + c4);
      const float4 vv = *(const float4*)(Vg + (size_t)(j0 + key) * HD + c4);
      const float ka[4] = {kv.x, kv.y, kv.z, kv.w};
      const float va[4] = {vv.x, vv.y, vv.z, vv.w};
      const int kst = key >> 3;
      const int kidx = kst * 4 + (key & 3);
      const int kcomp = (key >> 2) & 1;
#pragma unroll
      for (int j = 0; j < 4; ++j) {
        const int d = c4 + j;
        uint32_t hv, lv;
        // K element (key, d)
        split1(ka[j], hv, lv);
        const int ks = d >> 3;
        const int idx = ks * 4 + (d & 3);
        const int comp = (d >> 2) & 1;
        ((uint32_t*)&sm->K2h[key][idx])[comp] = hv;
        ((uint32_t*)&sm->K2l[key][idx])[comp] = lv;
        // V element (key, d) -> V2[d][kidx]
        split1(va[j], hv, lv);
        ((uint32_t*)&sm->V2h[d][kidx])[kcomp] = hv;
        ((uint32_t*)&sm->V2l[d][kidx])[kcomp] = lv;
      }
    }
    __syncthreads();

    // ---- S = Q @ K^T (raw), 4 n-tiles of 8 keys ----
    float s[4][4] = {};
#pragma unroll
    for (int nt = 0; nt < 4; ++nt) {
#pragma unroll
      for (int ks = 0; ks < 8; ++ks) {
        const uint2 bhv = sm->K2h[nt * 8 + grp][ks * 4 + qp];
        const uint2 blv = sm->K2l[nt * 8 + grp][ks * 4 + qp];
        uint32_t bh2[2] = {bhv.x, bhv.y};
        uint32_t bl2[2] = {blv.x, blv.y};
        mma_tf32(s[nt], qh[ks], bh2);
        mma_tf32(s[nt], qh[ks], bl2);
        mma_tf32(s[nt], ql[ks], bh2);
      }
    }

    // ---- online softmax (rows qrow, qrow+8 per lane-group) ----
    float mx0 = -1e30f, mx1 = -1e30f;
#pragma unroll
    for (int nt = 0; nt < 4; ++nt) {
      mx0 = fmaxf(mx0, fmaxf(s[nt][0], s[nt][1]));
      mx1 = fmaxf(mx1, fmaxf(s[nt][2], s[nt][3]));
    }
    mx0 = fmaxf(mx0, __shfl_xor_sync(0xffffffffu, mx0, 1));
    mx0 = fmaxf(mx0, __shfl_xor_sync(0xffffffffu, mx0, 2));
    mx1 = fmaxf(mx1, __shfl_xor_sync(0xffffffffu, mx1, 1));
    mx1 = fmaxf(mx1, __shfl_xor_sync(0xffffffffu, mx1, 2));
    const float mn0 = fmaxf(m0v, mx0 * SCALE);
    const float mn1 = fmaxf(m1v, mx1 * SCALE);
    const float c0 = __expf(m0v - mn0);
    const float c1 = __expf(m1v - mn1);
    m0v = mn0; m1v = mn1;

    float ls0 = 0.f, ls1 = 0.f;
    float p[4][4];
#pragma unroll
    for (int nt = 0; nt < 4; ++nt) {
      p[nt][0] = __expf(s[nt][0] * SCALE - mn0);
      p[nt][1] = __expf(s[nt][1] * SCALE - mn0);
      p[nt][2] = __expf(s[nt][2] * SCALE - mn1);
      p[nt][3] = __expf(s[nt][3] * SCALE - mn1);
      ls0 += p[nt][0] + p[nt][1];
      ls1 += p[nt][2] + p[nt][3];
    }
    ls0 += __shfl_xor_sync(0xffffffffu, ls0, 1);
    ls0 += __shfl_xor_sync(0xffffffffu, ls0, 2);
    ls1 += __shfl_xor_sync(0xffffffffu, ls1, 1);
    ls1 += __shfl_xor_sync(0xffffffffu, ls1, 2);
    l0v = l0v * c0 + ls0;
    l1v = l1v * c1 + ls1;

    // rescale O
#pragma unroll
    for (int nt2 = 0; nt2 < 8; ++nt2) {
      o[nt2][0] *= c0; o[nt2][1] *= c0;
      o[nt2][2] *= c1; o[nt2][3] *= c1;
    }

    // ---- stage P (split) into warp-private smem rows ----
#pragma unroll
    for (int nt = 0; nt < 4; ++nt) {
#pragma unroll
      for (int j = 0; j < 2; ++j) {
        const int col = nt * 8 + qp * 2 + j;
        const int kst = col >> 3;
        const int idx = kst * 4 + (col & 3);
        const int comp = (col >> 2) & 1;
        uint32_t hv, lv;
        split1(p[nt][j], hv, lv);       // row qrow
        ((uint32_t*)&sm->P2h[qrow][idx])[comp] = hv;
        ((uint32_t*)&sm->P2l[qrow][idx])[comp] = lv;
        split1(p[nt][2 + j], hv, lv);   // row qrow+8
        ((uint32_t*)&sm->P2h[qrow + 8][idx])[comp] = hv;
        ((uint32_t*)&sm->P2l[qrow + 8][idx])[comp] = lv;
      }
    }
    __syncwarp();

    // ---- O += P @ V ----
#pragma unroll
    for (int kst = 0; kst < 4; ++kst) {
      const uint2 pa0h = sm->P2h[qrow][kst * 4 + qp];
      const uint2 pa1h = sm->P2h[qrow + 8][kst * 4 + qp];
      const uint2 pa0l = sm->P2l[qrow][kst * 4 + qp];
      const uint2 pa1l = sm->P2l[qrow + 8][kst * 4 + qp];
      uint32_t ah2[4] = {pa0h.x, pa1h.x, pa0h.y, pa1h.y};
      uint32_t al2[4] = {pa0l.x, pa1l.x, pa0l.y, pa1l.y};
#pragma unroll
      for (int nt2 = 0; nt2 < 8; ++nt2) {
        const uint2 vbh = sm->V2h[nt2 * 8 + grp][kst * 4 + qp];
        const uint2 vbl = sm->V2l[nt2 * 8 + grp][kst * 4 + qp];
        uint32_t bh2[2] = {vbh.x, vbh.y};
        uint32_t bl2[2] = {vbl.x, vbl.y};
        mma_tf32(o[nt2], ah2, bh2);
        mma_tf32(o[nt2], ah2, bl2);
        mma_tf32(o[nt2], al2, bh2);
      }
    }
  }

  // ---- epilogue: divide by l, store to g_ao [b][s][h*64+d] ----
  const float il0 = 1.f / l0v;
  const float il1 = 1.f / l1v;
  float* aob = g_ao + ((size_t)(b * SEQ + q0) ) * EMB + h * HD;
#pragma unroll
  for (int nt2 = 0; nt2 < 8; ++nt2) {
    const int d0 = nt2 * 8 + qp * 2;
    float2 v0 = {o[nt2][0] * il0, o[nt2][1] * il0};
    float2 v1 = {o[nt2][2] * il1, o[nt2][3] * il1};
    *(float2*)(aob + (size_t)qrow * EMB + d0) = v0;
    *(float2*)(aob + (size_t)(qrow + 8) * EMB + d0) = v1;
  }
}

// ---------------------------------------------------------------------------
extern "C" void kernel_launch(void* const* d_in, const int* in_sizes, int n_in,
                              void* d_out, int out_size) {
  (void)in_sizes; (void)n_in; (void)out_size;
  const float* query = (const float*)d_in[0];
  // d_in[1]=key, d_in[2]=value: ignored by the reference module
  const float* Wqkv = (const float*)d_in[3];
  const float* bqkv = (const float*)d_in[4];
  const float* Wout = (const float*)d_in[5];
  const float* bout = (const float*)d_in[6];
  float* out = (float*)d_out;

  cudaFuncSetAttribute(flash_mma_kernel,
                       cudaFuncAttributeMaxDynamicSharedMemorySize,
                       (int)ATTN_SMEM_BYTES);

  dim3 g1(24, 64);   // 3072/128 x 8192/128
  gemm_mma_kernel<0><<<g1, 256>>>(query, Wqkv, bqkv, nullptr);

  dim3 g2(64, 32);   // (b*h) x (S/64)
  flash_mma_kernel<<<g2, 128, ATTN_SMEM_BYTES>>>();

  dim3 g3(8, 64);    // 1024/128 x 8192/128
  gemm_mma_kernel<1><<<g3, 256>>>(nullptr, Wout, bout, out);
}

// round 6
// speedup vs baseline: 1.6849x; 1.6849x over previous
#include <cuda_runtime.h>
#include <cstdint>

#define BB 4
#define SEQ 2048
#define EMB 1024
#define NH 16
#define HD 64
#define MT (BB * SEQ)  // 8192 tokens

// Scratch (allocation-free rule: device globals)
__device__ float g_q[BB * NH * SEQ * HD];   // [b][h][s][d]
__device__ float g_k[BB * NH * SEQ * HD];
__device__ float g_v[BB * NH * SEQ * HD];
__device__ float g_ao[MT * EMB];            // attention out, [b][s][h*64+d] == [m][e]

// ---------------------------------------------------------------------------
// tf32 helpers (baseline PTX, works at .target sm_100)
// ---------------------------------------------------------------------------
__device__ __forceinline__ uint32_t f2tf32(float x) {
  uint32_t r;
  asm("cvt.rna.tf32.f32 %0, %1;" : "=r"(r) : "f"(x));
  return r;
}

__device__ __forceinline__ void split1(float v, uint32_t& h, uint32_t& l) {
  h = f2tf32(v);
  l = f2tf32(v - __uint_as_float(h));
}

__device__ __forceinline__ void mma_tf32(float* c, const uint32_t* a,
                                         const uint32_t* b) {
  asm volatile(
      "mma.sync.aligned.m16n8k8.row.col.f32.tf32.tf32.f32 "
      "{%0,%1,%2,%3}, {%4,%5,%6,%7}, {%8,%9}, {%0,%1,%2,%3};"
      : "+f"(c[0]), "+f"(c[1]), "+f"(c[2]), "+f"(c[3])
      : "r"(a[0]), "r"(a[1]), "r"(a[2]), "r"(a[3]), "r"(b[0]), "r"(b[1]));
}

// ---------------------------------------------------------------------------
// tf32 3x-split GEMM via mma.sync (UNCHANGED from R3/R4 — known good):
// D[m][n] = sum_k A[m][k]*B[n][k] + bias[n]
// CTA 128x128, BK=16, 256 threads (8 warps, each 64x32 out).
// MODE 0: A=query, scatter into g_q/g_k/g_v. MODE 1: A=g_ao, write out.
// ---------------------------------------------------------------------------
#define SPAD 20  // row stride in words for 16-col tile (conflict-free frags)

template <int MODE>
__global__ __launch_bounds__(256) void gemm_mma_kernel(
    const float* __restrict__ A, const float* __restrict__ B,
    const float* __restrict__ bias, float* __restrict__ out) {
  __shared__ uint32_t s_ahi[128 * SPAD];
  __shared__ uint32_t s_alo[128 * SPAD];
  __shared__ uint32_t s_bhi[128 * SPAD];
  __shared__ uint32_t s_blo[128 * SPAD];

  const int tid = threadIdx.x;
  const int lane = tid & 31;
  const int wid = tid >> 5;
  const int warp_m = wid & 1;        // 2 warps over M
  const int warp_n = wid >> 1;       // 4 warps over N
  const int m0 = blockIdx.y * 128;
  const int n0 = blockIdx.x * 128;

  const float* Asrc = (MODE == 0) ? A : g_ao;

  const int ldr = tid >> 2;          // rows 0..63 (+64 for second half)
  const int ldc = (tid & 3) * 4;     // 0,4,8,12

  const float* Ap0 = Asrc + (size_t)(m0 + ldr) * EMB + ldc;
  const float* Ap1 = Asrc + (size_t)(m0 + 64 + ldr) * EMB + ldc;
  const float* Bp0 = B + (size_t)(n0 + ldr) * EMB + ldc;
  const float* Bp1 = B + (size_t)(n0 + 64 + ldr) * EMB + ldc;

  float acc[4][4][4] = {};  // [mt][nt][reg]

  float4 pa0, pa1, pb0, pb1;
  pa0 = *(const float4*)(Ap0);
  pa1 = *(const float4*)(Ap1);
  pb0 = *(const float4*)(Bp0);
  pb1 = *(const float4*)(Bp1);

  const int s0 = ldr * SPAD + ldc;
  const int s1 = (ldr + 64) * SPAD + ldc;

  for (int c = 0; c < EMB / 16; ++c) {
    if (c > 0) __syncthreads();

    {
      uint4 h, l;
      split1(pa0.x, h.x, l.x); split1(pa0.y, h.y, l.y);
      split1(pa0.z, h.z, l.z); split1(pa0.w, h.w, l.w);
      *(uint4*)&s_ahi[s0] = h; *(uint4*)&s_alo[s0] = l;
      split1(pa1.x, h.x, l.x); split1(pa1.y, h.y, l.y);
      split1(pa1.z, h.z, l.z); split1(pa1.w, h.w, l.w);
      *(uint4*)&s_ahi[s1] = h; *(uint4*)&s_alo[s1] = l;
      split1(pb0.x, h.x, l.x); split1(pb0.y, h.y, l.y);
      split1(pb0.z, h.z, l.z); split1(pb0.w, h.w, l.w);
      *(uint4*)&s_bhi[s0] = h; *(uint4*)&s_blo[s0] = l;
      split1(pb1.x, h.x, l.x); split1(pb1.y, h.y, l.y);
      split1(pb1.z, h.z, l.z); split1(pb1.w, h.w, l.w);
      *(uint4*)&s_bhi[s1] = h; *(uint4*)&s_blo[s1] = l;
    }
    __syncthreads();

    if (c + 1 < EMB / 16) {
      const int off = (c + 1) * 16;
      pa0 = *(const float4*)(Ap0 + off);
      pa1 = *(const float4*)(Ap1 + off);
      pb0 = *(const float4*)(Bp0 + off);
      pb1 = *(const float4*)(Bp1 + off);
    }

#pragma unroll
    for (int kc = 0; kc < 2; ++kc) {
      const int kb = kc * 8 + (lane & 3);
      uint32_t ah[4][4], al[4][4];
#pragma unroll
      for (int mt = 0; mt < 4; ++mt) {
        const int r = warp_m * 64 + mt * 16 + (lane >> 2);
        const int i0 = r * SPAD + kb;
        const int i1 = (r + 8) * SPAD + kb;
        ah[mt][0] = s_ahi[i0];     ah[mt][1] = s_ahi[i1];
        ah[mt][2] = s_ahi[i0 + 4]; ah[mt][3] = s_ahi[i1 + 4];
        al[mt][0] = s_alo[i0];     al[mt][1] = s_alo[i1];
        al[mt][2] = s_alo[i0 + 4]; al[mt][3] = s_alo[i1 + 4];
      }
      uint32_t bh[4][2], bl[4][2];
#pragma unroll
      for (int nt = 0; nt < 4; ++nt) {
        const int n = warp_n * 32 + nt * 8 + (lane >> 2);
        const int i0 = n * SPAD + kb;
        bh[nt][0] = s_bhi[i0]; bh[nt][1] = s_bhi[i0 + 4];
        bl[nt][0] = s_blo[i0]; bl[nt][1] = s_blo[i0 + 4];
      }
#pragma unroll
      for (int mt = 0; mt < 4; ++mt)
#pragma unroll
        for (int nt = 0; nt < 4; ++nt) {
          mma_tf32(acc[mt][nt], ah[mt], bh[nt]);
          mma_tf32(acc[mt][nt], ah[mt], bl[nt]);
          mma_tf32(acc[mt][nt], al[mt], bh[nt]);
        }
    }
  }

#pragma unroll
  for (int mt = 0; mt < 4; ++mt) {
#pragma unroll
    for (int nt = 0; nt < 4; ++nt) {
      const int r = m0 + warp_m * 64 + mt * 16 + (lane >> 2);
      const int n = n0 + warp_n * 32 + nt * 8 + (lane & 3) * 2;
      const float b0 = bias[n], b1 = bias[n + 1];
      float2 v0 = {acc[mt][nt][0] + b0, acc[mt][nt][1] + b1};
      float2 v1 = {acc[mt][nt][2] + b0, acc[mt][nt][3] + b1};
      if (MODE == 0) {
        const int which = n >> 10;
        float* dstv = (which == 0) ? g_q : (which == 1) ? g_k : g_v;
        const int rem = n & 1023;
        const int h = rem >> 6;
        const int d = rem & 63;
        const int b_ = r >> 11, s_ = r & 2047;
        float* base = dstv + (size_t)(((b_ << 4) + h) * SEQ) * HD + d;
        *(float2*)(base + (size_t)s_ * HD) = v0;
        *(float2*)(base + (size_t)(s_ + 8) * HD) = v1;
      } else {
        *(float2*)(out + (size_t)r * EMB + n) = v0;
        *(float2*)(out + (size_t)(r + 8) * EMB + n) = v1;
      }
    }
  }
}

// ---------------------------------------------------------------------------
// Flash attention v2: plain tf32 mma (no 3x split), CTA = 128 q-rows,
// 256 threads / 8 warps (warp w owns rows w*16..w*16+15), KV tiles of 32.
// Packed uint2 fragment layouts (conflict-free LDS.64):
//   K2[key][ks*4+qp]  = (K[key][ks*8+qp],   K[key][ks*8+qp+4])
//   V2[d][kst*4+qp]   = (V[kst*8+qp][d],    V[kst*8+qp+4][d])
//   P2[row][kst*4+qp] = (P[row][kst*8+qp],  P[row][kst*8+qp+4])
// Row strides 36/20/20 uint2 -> stride ≡ 8 (mod 32) words.
// scores scaled by 1/sqrt(EMB) = 1/32.
// ---------------------------------------------------------------------------
struct AttnSmem {
  union {
    float Qs[128][68];      // 34816 B staging (used once at start)
    struct {
      uint2 K2[32][36];     // 9216 B
      uint2 V2[64][20];     // 10240 B
      uint2 P2[128][20];    // 20480 B
    } t;
  };
};
#define ATTN_SMEM_BYTES sizeof(AttnSmem)

__global__ __launch_bounds__(256, 2) void flash_mma_kernel() {
  extern __shared__ char dsm_raw[];
  AttnSmem* sm = reinterpret_cast<AttnSmem*>(dsm_raw);

  const int tid = threadIdx.x;
  const int lane = tid & 31;
  const int w = tid >> 5;
  const int grp = lane >> 2;     // 0..7
  const int qp = lane & 3;       // 0..3
  const int bh = blockIdx.x;     // 0..63
  const int q0 = blockIdx.y * 128;
  const int b = bh >> 4, h = bh & 15;
  const int qrow = w * 16 + grp;

  const float* Qg = g_q + (size_t)(bh * SEQ + q0) * HD;
  const float* Kg = g_k + (size_t)bh * SEQ * HD;
  const float* Vg = g_v + (size_t)bh * SEQ * HD;

  // ---- stage Q tile (128x64) to smem, coalesced ----
#pragma unroll
  for (int it = 0; it < 8; ++it) {
    const int slot = it * 256 + tid;   // 0..2047 float4 slots
    const int r = slot >> 4;
    const int c = (slot & 15) * 4;
    *(float4*)&sm->Qs[r][c] = *(const float4*)(Qg + r * HD + c);
  }
  __syncthreads();

  // ---- per-thread Q fragments (regs, whole CTA lifetime) ----
  uint32_t qf[8][4];
#pragma unroll
  for (int ks = 0; ks < 8; ++ks) {
    qf[ks][0] = f2tf32(sm->Qs[qrow][ks * 8 + qp]);
    qf[ks][1] = f2tf32(sm->Qs[qrow + 8][ks * 8 + qp]);
    qf[ks][2] = f2tf32(sm->Qs[qrow][ks * 8 + qp + 4]);
    qf[ks][3] = f2tf32(sm->Qs[qrow + 8][ks * 8 + qp + 4]);
  }

  float o[8][4] = {};                  // O accum [d-tile][reg]
  float m0v = -1e30f, m1v = -1e30f;    // row maxima (scaled domain)
  float l0v = 0.f, l1v = 0.f;
  const float SCALE = 0.03125f;        // 1/sqrt(1024)

  for (int j0 = 0; j0 < SEQ; j0 += 32) {
    __syncthreads();   // K/V/Q-staging consumed by previous phase

    // ---- load + cvt K,V tile (32 keys x 64 d) into packed layouts ----
#pragma unroll
    for (int it = 0; it < 2; ++it) {
      const int slot = it * 256 + tid;  // 0..511 float4 slots
      const int key = slot >> 4;        // 0..31
      const int c4 = (slot & 15) * 4;   // 0..60
      const float4 kv = *(const float4*)(Kg + (size_t)(j0 + key) * HD + c4);
      const float4 vv = *(const float4*)(Vg + (size_t)(j0 + key) * HD + c4);
      const float ka[4] = {kv.x, kv.y, kv.z, kv.w};
      const float va[4] = {vv.x, vv.y, vv.z, vv.w};
      const int kst = key >> 3;
      const int kidx = kst * 4 + (key & 3);
      const int kcomp = (key >> 2) & 1;
#pragma unroll
      for (int j = 0; j < 4; ++j) {
        const int d = c4 + j;
        const int ks = d >> 3;
        const int idx = ks * 4 + (d & 3);
        const int comp = (d >> 2) & 1;
        ((uint32_t*)&sm->t.K2[key][idx])[comp] = f2tf32(ka[j]);
        ((uint32_t*)&sm->t.V2[d][kidx])[kcomp] = f2tf32(va[j]);
      }
    }
    __syncthreads();

    // ---- S = Q @ K^T (raw), 4 n-tiles of 8 keys ----
    float s[4][4] = {};
#pragma unroll
    for (int nt = 0; nt < 4; ++nt) {
#pragma unroll
      for (int ks = 0; ks < 8; ++ks) {
        const uint2 bv = sm->t.K2[nt * 8 + grp][ks * 4 + qp];
        uint32_t b2[2] = {bv.x, bv.y};
        mma_tf32(s[nt], qf[ks], b2);
      }
    }

    // ---- online softmax (rows qrow, qrow+8 per lane-group) ----
    float mx0 = -1e30f, mx1 = -1e30f;
#pragma unroll
    for (int nt = 0; nt < 4; ++nt) {
      mx0 = fmaxf(mx0, fmaxf(s[nt][0], s[nt][1]));
      mx1 = fmaxf(mx1, fmaxf(s[nt][2], s[nt][3]));
    }
    mx0 = fmaxf(mx0, __shfl_xor_sync(0xffffffffu, mx0, 1));
    mx0 = fmaxf(mx0, __shfl_xor_sync(0xffffffffu, mx0, 2));
    mx1 = fmaxf(mx1, __shfl_xor_sync(0xffffffffu, mx1, 1));
    mx1 = fmaxf(mx1, __shfl_xor_sync(0xffffffffu, mx1, 2));
    const float mn0 = fmaxf(m0v, mx0 * SCALE);
    const float mn1 = fmaxf(m1v, mx1 * SCALE);
    const float c0 = __expf(m0v - mn0);
    const float c1 = __expf(m1v - mn1);
    m0v = mn0; m1v = mn1;

    float ls0 = 0.f, ls1 = 0.f;
    float p[4][4];
#pragma unroll
    for (int nt = 0; nt < 4; ++nt) {
      p[nt][0] = __expf(s[nt][0] * SCALE - mn0);
      p[nt][1] = __expf(s[nt][1] * SCALE - mn0);
      p[nt][2] = __expf(s[nt][2] * SCALE - mn1);
      p[nt][3] = __expf(s[nt][3] * SCALE - mn1);
      ls0 += p[nt][0] + p[nt][1];
      ls1 += p[nt][2] + p[nt][3];
    }
    ls0 += __shfl_xor_sync(0xffffffffu, ls0, 1);
    ls0 += __shfl_xor_sync(0xffffffffu, ls0, 2);
    ls1 += __shfl_xor_sync(0xffffffffu, ls1, 1);
    ls1 += __shfl_xor_sync(0xffffffffu, ls1, 2);
    l0v = l0v * c0 + ls0;
    l1v = l1v * c1 + ls1;

    // rescale O
#pragma unroll
    for (int dt = 0; dt < 8; ++dt) {
      o[dt][0] *= c0; o[dt][1] *= c0;
      o[dt][2] *= c1; o[dt][3] *= c1;
    }

    // ---- stage P (tf32) into warp-private smem rows ----
#pragma unroll
    for (int nt = 0; nt < 4; ++nt) {
#pragma unroll
      for (int j = 0; j < 2; ++j) {
        const int col = nt * 8 + qp * 2 + j;
        const int kst = col >> 3;
        const int idx = kst * 4 + (col & 3);
        const int comp = (col >> 2) & 1;
        ((uint32_t*)&sm->t.P2[qrow][idx])[comp] = f2tf32(p[nt][j]);
        ((uint32_t*)&sm->t.P2[qrow + 8][idx])[comp] = f2tf32(p[nt][2 + j]);
      }
    }
    __syncwarp();

    // ---- O += P @ V ----
#pragma unroll
    for (int kst = 0; kst < 4; ++kst) {
      const uint2 pa0 = sm->t.P2[qrow][kst * 4 + qp];
      const uint2 pa1 = sm->t.P2[qrow + 8][kst * 4 + qp];
      uint32_t a2[4] = {pa0.x, pa1.x, pa0.y, pa1.y};
#pragma unroll
      for (int dt = 0; dt < 8; ++dt) {
        const uint2 vb = sm->t.V2[dt * 8 + grp][kst * 4 + qp];
        uint32_t b2[2] = {vb.x, vb.y};
        mma_tf32(o[dt], a2, b2);
      }
    }
  }

  // ---- epilogue: divide by l, store to g_ao [b][s][h*64+d] ----
  const float il0 = 1.f / l0v;
  const float il1 = 1.f / l1v;
  float* aob = g_ao + ((size_t)(b * SEQ + q0)) * EMB + h * HD;
#pragma unroll
  for (int dt = 0; dt < 8; ++dt) {
    const int d0 = dt * 8 + qp * 2;
    float2 v0 = {o[dt][0] * il0, o[dt][1] * il0};
    float2 v1 = {o[dt][2] * il1, o[dt][3] * il1};
    *(float2*)(aob + (size_t)qrow * EMB + d0) = v0;
    *(float2*)(aob + (size_t)(qrow + 8) * EMB + d0) = v1;
  }
}

// ---------------------------------------------------------------------------
extern "C" void kernel_launch(void* const* d_in, const int* in_sizes, int n_in,
                              void* d_out, int out_size) {
  (void)in_sizes; (void)n_in; (void)out_size;
  const float* query = (const float*)d_in[0];
  // d_in[1]=key, d_in[2]=value: ignored by the reference module
  const float* Wqkv = (const float*)d_in[3];
  const float* bqkv = (const float*)d_in[4];
  const float* Wout = (const float*)d_in[5];
  const float* bout = (const float*)d_in[6];
  float* out = (float*)d_out;

  cudaFuncSetAttribute(flash_mma_kernel,
                       cudaFuncAttributeMaxDynamicSharedMemorySize,
                       (int)ATTN_SMEM_BYTES);

  dim3 g1(24, 64);   // 3072/128 x 8192/128
  gemm_mma_kernel<0><<<g1, 256>>>(query, Wqkv, bqkv, nullptr);

  dim3 g2(64, 16);   // (b*h) x (S/128)
  flash_mma_kernel<<<g2, 256, ATTN_SMEM_BYTES>>>();

  dim3 g3(8, 64);    // 1024/128 x 8192/128
  gemm_mma_kernel<1><<<g3, 256>>>(nullptr, Wout, bout, out);
}

// round 7
// speedup vs baseline: 1.8193x; 1.0798x over previous
#include <cuda_runtime.h>
#include <cstdint>

#define BB 4
#define SEQ 2048
#define EMB 1024
#define NH 16
#define HD 64
#define MT (BB * SEQ)  // 8192 tokens

// Scratch (allocation-free rule: device globals)
__device__ float g_q[BB * NH * SEQ * HD];   // [b][h][s][d]
__device__ float g_k[BB * NH * SEQ * HD];
__device__ float g_v[BB * NH * SEQ * HD];
__device__ float g_ao[MT * EMB];            // attention out, [b][s][h*64+d] == [m][e]

// ---------------------------------------------------------------------------
// tf32 helpers (baseline PTX, works at .target sm_100)
// ---------------------------------------------------------------------------
__device__ __forceinline__ uint32_t f2tf32(float x) {
  uint32_t r;
  asm("cvt.rna.tf32.f32 %0, %1;" : "=r"(r) : "f"(x));
  return r;
}

__device__ __forceinline__ void split1(float v, uint32_t& h, uint32_t& l) {
  h = f2tf32(v);
  l = f2tf32(v - __uint_as_float(h));
}

__device__ __forceinline__ void mma_tf32(float* c, const uint32_t* a,
                                         const uint32_t* b) {
  asm volatile(
      "mma.sync.aligned.m16n8k8.row.col.f32.tf32.tf32.f32 "
      "{%0,%1,%2,%3}, {%4,%5,%6,%7}, {%8,%9}, {%0,%1,%2,%3};"
      : "+f"(c[0]), "+f"(c[1]), "+f"(c[2]), "+f"(c[3])
      : "r"(a[0]), "r"(a[1]), "r"(a[2]), "r"(a[3]), "r"(b[0]), "r"(b[1]));
}

// ---------------------------------------------------------------------------
// tf32 3x-split GEMM, double-buffered smem, ONE sync per BK=16 chunk.
// D[m][n] = sum_k A[m][k]*B[n][k] + bias[n]
// CTA 128x128, 256 threads (8 warps, each 64x32 out).
// MODE 0: A=query, scatter into g_q/g_k/g_v. MODE 1: A=g_ao, write out.
// ---------------------------------------------------------------------------
#define SPAD 20                 // row stride in words (conflict-free frags)
#define BUFW (128 * SPAD)       // one tile in words
#define GEMM_SMEM_BYTES (2 * 4 * BUFW * 4)  // 2 buffers x 4 tiles x words x 4B

template <int MODE>
__global__ __launch_bounds__(256) void gemm_mma_kernel(
    const float* __restrict__ A, const float* __restrict__ B,
    const float* __restrict__ bias, float* __restrict__ out) {
  extern __shared__ uint32_t gsm[];

  const int tid = threadIdx.x;
  const int lane = tid & 31;
  const int wid = tid >> 5;
  const int warp_m = wid & 1;        // 2 warps over M
  const int warp_n = wid >> 1;       // 4 warps over N
  const int m0 = blockIdx.y * 128;
  const int n0 = blockIdx.x * 128;

  const float* Asrc = (MODE == 0) ? A : g_ao;

  const int ldr = tid >> 2;          // rows 0..63 (+64 for second half)
  const int ldc = (tid & 3) * 4;     // 0,4,8,12

  const float* Ap0 = Asrc + (size_t)(m0 + ldr) * EMB + ldc;
  const float* Ap1 = Asrc + (size_t)(m0 + 64 + ldr) * EMB + ldc;
  const float* Bp0 = B + (size_t)(n0 + ldr) * EMB + ldc;
  const float* Bp1 = B + (size_t)(n0 + 64 + ldr) * EMB + ldc;

  float acc[4][4][4] = {};  // [mt][nt][reg]

  const int s0 = ldr * SPAD + ldc;
  const int s1 = (ldr + 64) * SPAD + ldc;

  float4 pa0 = *(const float4*)(Ap0);
  float4 pa1 = *(const float4*)(Ap1);
  float4 pb0 = *(const float4*)(Bp0);
  float4 pb1 = *(const float4*)(Bp1);

  // prologue: split+store chunk 0 into buffer 0
  {
    uint32_t* ahi = gsm;
    uint32_t* alo = gsm + BUFW;
    uint32_t* bhi = gsm + 2 * BUFW;
    uint32_t* blo = gsm + 3 * BUFW;
    uint4 h, l;
    split1(pa0.x, h.x, l.x); split1(pa0.y, h.y, l.y);
    split1(pa0.z, h.z, l.z); split1(pa0.w, h.w, l.w);
    *(uint4*)&ahi[s0] = h; *(uint4*)&alo[s0] = l;
    split1(pa1.x, h.x, l.x); split1(pa1.y, h.y, l.y);
    split1(pa1.z, h.z, l.z); split1(pa1.w, h.w, l.w);
    *(uint4*)&ahi[s1] = h; *(uint4*)&alo[s1] = l;
    split1(pb0.x, h.x, l.x); split1(pb0.y, h.y, l.y);
    split1(pb0.z, h.z, l.z); split1(pb0.w, h.w, l.w);
    *(uint4*)&bhi[s0] = h; *(uint4*)&blo[s0] = l;
    split1(pb1.x, h.x, l.x); split1(pb1.y, h.y, l.y);
    split1(pb1.z, h.z, l.z); split1(pb1.w, h.w, l.w);
    *(uint4*)&bhi[s1] = h; *(uint4*)&blo[s1] = l;
  }

  for (int c = 0; c < EMB / 16; ++c) {
    __syncthreads();  // stores of chunk c done; computes of chunk c-1 done

    const bool more = (c + 1 < EMB / 16);
    if (more) {
      const int off = (c + 1) * 16;
      pa0 = *(const float4*)(Ap0 + off);
      pa1 = *(const float4*)(Ap1 + off);
      pb0 = *(const float4*)(Bp0 + off);
      pb1 = *(const float4*)(Bp1 + off);
    }

    // compute chunk c from buffer c&1
    {
      const uint32_t* cb = gsm + (c & 1) * (4 * BUFW);
      const uint32_t* s_ahi = cb;
      const uint32_t* s_alo = cb + BUFW;
      const uint32_t* s_bhi = cb + 2 * BUFW;
      const uint32_t* s_blo = cb + 3 * BUFW;
#pragma unroll
      for (int kc = 0; kc < 2; ++kc) {
        const int kb = kc * 8 + (lane & 3);
        uint32_t ah[4][4], al[4][4];
#pragma unroll
        for (int mt = 0; mt < 4; ++mt) {
          const int r = warp_m * 64 + mt * 16 + (lane >> 2);
          const int i0 = r * SPAD + kb;
          const int i1 = (r + 8) * SPAD + kb;
          ah[mt][0] = s_ahi[i0];     ah[mt][1] = s_ahi[i1];
          ah[mt][2] = s_ahi[i0 + 4]; ah[mt][3] = s_ahi[i1 + 4];
          al[mt][0] = s_alo[i0];     al[mt][1] = s_alo[i1];
          al[mt][2] = s_alo[i0 + 4]; al[mt][3] = s_alo[i1 + 4];
        }
        uint32_t bh[4][2], bl[4][2];
#pragma unroll
        for (int nt = 0; nt < 4; ++nt) {
          const int n = warp_n * 32 + nt * 8 + (lane >> 2);
          const int i0 = n * SPAD + kb;
          bh[nt][0] = s_bhi[i0]; bh[nt][1] = s_bhi[i0 + 4];
          bl[nt][0] = s_blo[i0]; bl[nt][1] = s_blo[i0 + 4];
        }
#pragma unroll
        for (int mt = 0; mt < 4; ++mt)
#pragma unroll
          for (int nt = 0; nt < 4; ++nt) {
            mma_tf32(acc[mt][nt], ah[mt], bh[nt]);
            mma_tf32(acc[mt][nt], ah[mt], bl[nt]);
            mma_tf32(acc[mt][nt], al[mt], bh[nt]);
          }
      }
    }

    // split+store chunk c+1 into the other buffer (holds c-1; its readers done)
    if (more) {
      uint32_t* nb = gsm + ((c + 1) & 1) * (4 * BUFW);
      uint32_t* ahi = nb;
      uint32_t* alo = nb + BUFW;
      uint32_t* bhi = nb + 2 * BUFW;
      uint32_t* blo = nb + 3 * BUFW;
      uint4 h, l;
      split1(pa0.x, h.x, l.x); split1(pa0.y, h.y, l.y);
      split1(pa0.z, h.z, l.z); split1(pa0.w, h.w, l.w);
      *(uint4*)&ahi[s0] = h; *(uint4*)&alo[s0] = l;
      split1(pa1.x, h.x, l.x); split1(pa1.y, h.y, l.y);
      split1(pa1.z, h.z, l.z); split1(pa1.w, h.w, l.w);
      *(uint4*)&ahi[s1] = h; *(uint4*)&alo[s1] = l;
      split1(pb0.x, h.x, l.x); split1(pb0.y, h.y, l.y);
      split1(pb0.z, h.z, l.z); split1(pb0.w, h.w, l.w);
      *(uint4*)&bhi[s0] = h; *(uint4*)&blo[s0] = l;
      split1(pb1.x, h.x, l.x); split1(pb1.y, h.y, l.y);
      split1(pb1.z, h.z, l.z); split1(pb1.w, h.w, l.w);
      *(uint4*)&bhi[s1] = h; *(uint4*)&blo[s1] = l;
    }
  }

#pragma unroll
  for (int mt = 0; mt < 4; ++mt) {
#pragma unroll
    for (int nt = 0; nt < 4; ++nt) {
      const int r = m0 + warp_m * 64 + mt * 16 + (lane >> 2);
      const int n = n0 + warp_n * 32 + nt * 8 + (lane & 3) * 2;
      const float b0 = bias[n], b1 = bias[n + 1];
      float2 v0 = {acc[mt][nt][0] + b0, acc[mt][nt][1] + b1};
      float2 v1 = {acc[mt][nt][2] + b0, acc[mt][nt][3] + b1};
      if (MODE == 0) {
        const int which = n >> 10;
        float* dstv = (which == 0) ? g_q : (which == 1) ? g_k : g_v;
        const int rem = n & 1023;
        const int h = rem >> 6;
        const int d = rem & 63;
        const int b_ = r >> 11, s_ = r & 2047;
        float* base = dstv + (size_t)(((b_ << 4) + h) * SEQ) * HD + d;
        *(float2*)(base + (size_t)s_ * HD) = v0;
        *(float2*)(base + (size_t)(s_ + 8) * HD) = v1;
      } else {
        *(float2*)(out + (size_t)r * EMB + n) = v0;
        *(float2*)(out + (size_t)(r + 8) * EMB + n) = v1;
      }
    }
  }
}

// ---------------------------------------------------------------------------
// Flash attention v3: plain tf32 mma, CTA = 128 q-rows, 256 threads / 8 warps,
// KV tiles of 32, K2/V2 DOUBLE-BUFFERED (one sync per tile), K/V prefetched to
// registers one tile ahead. Q pre-scaled by 1/sqrt(EMB)=1/32.
// Packed uint2 fragment layouts (conflict-free LDS.64), strides 36/20/20 uint2.
// smem (bytes): K2[2] @ 0,9216; V2[2] @ 18432,28672; P2 @ 38912; Qs overlays 0.
// ---------------------------------------------------------------------------
#define AT_K2_OFF 0
#define AT_V2_OFF (2 * 9216)
#define AT_P2_OFF (2 * 9216 + 2 * 10240)
#define ATTN_SMEM_BYTES (AT_P2_OFF + 128 * 20 * 8)  // 59392

__global__ __launch_bounds__(256, 2) void flash_mma_kernel() {
  extern __shared__ char asm_raw[];
  float (*Qs)[68] = reinterpret_cast<float(*)[68]>(asm_raw);
  uint2 (*P2)[20] = reinterpret_cast<uint2(*)[20]>(asm_raw + AT_P2_OFF);

  const int tid = threadIdx.x;
  const int lane = tid & 31;
  const int w = tid >> 5;
  const int grp = lane >> 2;     // 0..7
  const int qp = lane & 3;       // 0..3
  const int bh = blockIdx.x;     // 0..63
  const int q0 = blockIdx.y * 128;
  const int b = bh >> 4, h = bh & 15;
  const int qrow = w * 16 + grp;
  const float SCALE = 0.03125f;  // 1/sqrt(1024)

  const float* Qg = g_q + (size_t)(bh * SEQ + q0) * HD;
  const float* Kg = g_k + (size_t)bh * SEQ * HD;
  const float* Vg = g_v + (size_t)bh * SEQ * HD;

  // ---- stage Q tile (128x64) to smem, coalesced ----
#pragma unroll
  for (int it = 0; it < 8; ++it) {
    const int slot = it * 256 + tid;   // 0..2047 float4 slots
    const int r = slot >> 4;
    const int c = (slot & 15) * 4;
    *(float4*)&Qs[r][c] = *(const float4*)(Qg + r * HD + c);
  }
  __syncthreads();

  // ---- per-thread Q fragments, pre-scaled (regs, CTA lifetime) ----
  uint32_t qf[8][4];
#pragma unroll
  for (int ks = 0; ks < 8; ++ks) {
    qf[ks][0] = f2tf32(Qs[qrow][ks * 8 + qp] * SCALE);
    qf[ks][1] = f2tf32(Qs[qrow + 8][ks * 8 + qp] * SCALE);
    qf[ks][2] = f2tf32(Qs[qrow][ks * 8 + qp + 4] * SCALE);
    qf[ks][3] = f2tf32(Qs[qrow + 8][ks * 8 + qp + 4] * SCALE);
  }

  // loader mapping: this thread owns float4 slots {tid, 256+tid}
  const int key_a = tid >> 4;             // 0..15
  const int key_b = 16 + key_a;           // 16..31
  const int c4 = (tid & 15) * 4;          // 0..60

  // prefetch K/V tile 0
  float4 kra = *(const float4*)(Kg + (size_t)key_a * HD + c4);
  float4 krb = *(const float4*)(Kg + (size_t)key_b * HD + c4);
  float4 vra = *(const float4*)(Vg + (size_t)key_a * HD + c4);
  float4 vrb = *(const float4*)(Vg + (size_t)key_b * HD + c4);

  __syncthreads();  // all Q fragments extracted -> safe to overwrite Qs union

  // cvt+store helper data (computed once)
  // K element (key, d) -> K2[key][ (d>>3)*4 + (d&3) ] component (d>>2)&1
  // V element (key, d) -> V2[d][ (key>>3)*4 + (key&3) ] component (key>>2)&1
  float o[8][4] = {};
  float m0v = -1e30f, m1v = -1e30f;
  float l0v = 0.f, l1v = 0.f;

  // prologue: store tile 0 into buffer 0
  {
    uint2 (*K2)[36] = reinterpret_cast<uint2(*)[36]>(asm_raw + AT_K2_OFF);
    uint2 (*V2)[20] = reinterpret_cast<uint2(*)[20]>(asm_raw + AT_V2_OFF);
    const float ka0[4] = {kra.x, kra.y, kra.z, kra.w};
    const float kb0[4] = {krb.x, krb.y, krb.z, krb.w};
    const float va0[4] = {vra.x, vra.y, vra.z, vra.w};
    const float vb0[4] = {vrb.x, vrb.y, vrb.z, vrb.w};
    const int kidx_a = (key_a >> 3) * 4 + (key_a & 3);
    const int kcomp_a = (key_a >> 2) & 1;
    const int kidx_b = (key_b >> 3) * 4 + (key_b & 3);
    const int kcomp_b = (key_b >> 2) & 1;
#pragma unroll
    for (int j = 0; j < 4; ++j) {
      const int d = c4 + j;
      const int idx = (d >> 3) * 4 + (d & 3);
      const int comp = (d >> 2) & 1;
      ((uint32_t*)&K2[key_a][idx])[comp] = f2tf32(ka0[j]);
      ((uint32_t*)&K2[key_b][idx])[comp] = f2tf32(kb0[j]);
      ((uint32_t*)&V2[d][kidx_a])[kcomp_a] = f2tf32(va0[j]);
      ((uint32_t*)&V2[d][kidx_b])[kcomp_b] = f2tf32(vb0[j]);
    }
  }

  for (int jt = 0; jt < SEQ / 32; ++jt) {
    __syncthreads();  // tile jt stored by all; tile jt-1 readers done

    const bool more = (jt + 1 < SEQ / 32);
    if (more) {
      const size_t jb = (size_t)(jt + 1) * 32;
      kra = *(const float4*)(Kg + (jb + key_a) * HD + c4);
      krb = *(const float4*)(Kg + (jb + key_b) * HD + c4);
      vra = *(const float4*)(Vg + (jb + key_a) * HD + c4);
      vrb = *(const float4*)(Vg + (jb + key_b) * HD + c4);
    }

    const int cbuf = jt & 1;
    uint2 (*K2)[36] = reinterpret_cast<uint2(*)[36]>(asm_raw + AT_K2_OFF + cbuf * 9216);
    uint2 (*V2)[20] = reinterpret_cast<uint2(*)[20]>(asm_raw + AT_V2_OFF + cbuf * 10240);

    // ---- S = Q @ K^T (pre-scaled), 4 n-tiles of 8 keys ----
    float s[4][4] = {};
#pragma unroll
    for (int nt = 0; nt < 4; ++nt) {
#pragma unroll
      for (int ks = 0; ks < 8; ++ks) {
        const uint2 bv = K2[nt * 8 + grp][ks * 4 + qp];
        uint32_t b2[2] = {bv.x, bv.y};
        mma_tf32(s[nt], qf[ks], b2);
      }
    }

    // ---- online softmax ----
    float mx0 = -1e30f, mx1 = -1e30f;
#pragma unroll
    for (int nt = 0; nt < 4; ++nt) {
      mx0 = fmaxf(mx0, fmaxf(s[nt][0], s[nt][1]));
      mx1 = fmaxf(mx1, fmaxf(s[nt][2], s[nt][3]));
    }
    mx0 = fmaxf(mx0, __shfl_xor_sync(0xffffffffu, mx0, 1));
    mx0 = fmaxf(mx0, __shfl_xor_sync(0xffffffffu, mx0, 2));
    mx1 = fmaxf(mx1, __shfl_xor_sync(0xffffffffu, mx1, 1));
    mx1 = fmaxf(mx1, __shfl_xor_sync(0xffffffffu, mx1, 2));
    const float mn0 = fmaxf(m0v, mx0);
    const float mn1 = fmaxf(m1v, mx1);
    const float c0 = __expf(m0v - mn0);
    const float c1 = __expf(m1v - mn1);
    m0v = mn0; m1v = mn1;

    float ls0 = 0.f, ls1 = 0.f;
    float p[4][4];
#pragma unroll
    for (int nt = 0; nt < 4; ++nt) {
      p[nt][0] = __expf(s[nt][0] - mn0);
      p[nt][1] = __expf(s[nt][1] - mn0);
      p[nt][2] = __expf(s[nt][2] - mn1);
      p[nt][3] = __expf(s[nt][3] - mn1);
      ls0 += p[nt][0] + p[nt][1];
      ls1 += p[nt][2] + p[nt][3];
    }
    ls0 += __shfl_xor_sync(0xffffffffu, ls0, 1);
    ls0 += __shfl_xor_sync(0xffffffffu, ls0, 2);
    ls1 += __shfl_xor_sync(0xffffffffu, ls1, 1);
    ls1 += __shfl_xor_sync(0xffffffffu, ls1, 2);
    l0v = l0v * c0 + ls0;
    l1v = l1v * c1 + ls1;

#pragma unroll
    for (int dt = 0; dt < 8; ++dt) {
      o[dt][0] *= c0; o[dt][1] *= c0;
      o[dt][2] *= c1; o[dt][3] *= c1;
    }

    // ---- stage P (tf32) into warp-private smem rows ----
#pragma unroll
    for (int nt = 0; nt < 4; ++nt) {
#pragma unroll
      for (int j = 0; j < 2; ++j) {
        const int col = nt * 8 + qp * 2 + j;
        const int kst = col >> 3;
        const int idx = kst * 4 + (col & 3);
        const int comp = (col >> 2) & 1;
        ((uint32_t*)&P2[qrow][idx])[comp] = f2tf32(p[nt][j]);
        ((uint32_t*)&P2[qrow + 8][idx])[comp] = f2tf32(p[nt][2 + j]);
      }
    }
    __syncwarp();

    // ---- O += P @ V ----
#pragma unroll
    for (int kst = 0; kst < 4; ++kst) {
      const uint2 pa0 = P2[qrow][kst * 4 + qp];
      const uint2 pa1 = P2[qrow + 8][kst * 4 + qp];
      uint32_t a2[4] = {pa0.x, pa1.x, pa0.y, pa1.y};
#pragma unroll
      for (int dt = 0; dt < 8; ++dt) {
        const uint2 vb = V2[dt * 8 + grp][kst * 4 + qp];
        uint32_t b2[2] = {vb.x, vb.y};
        mma_tf32(o[dt], a2, b2);
      }
    }

    // ---- cvt+store tile jt+1 into other buffer (tile jt-1's readers done) ----
    if (more) {
      uint2 (*K2n)[36] = reinterpret_cast<uint2(*)[36]>(asm_raw + AT_K2_OFF + (cbuf ^ 1) * 9216);
      uint2 (*V2n)[20] = reinterpret_cast<uint2(*)[20]>(asm_raw + AT_V2_OFF + (cbuf ^ 1) * 10240);
      const float ka0[4] = {kra.x, kra.y, kra.z, kra.w};
      const float kb0[4] = {krb.x, krb.y, krb.z, krb.w};
      const float va0[4] = {vra.x, vra.y, vra.z, vra.w};
      const float vb0[4] = {vrb.x, vrb.y, vrb.z, vrb.w};
      const int kidx_a = (key_a >> 3) * 4 + (key_a & 3);
      const int kcomp_a = (key_a >> 2) & 1;
      const int kidx_b = (key_b >> 3) * 4 + (key_b & 3);
      const int kcomp_b = (key_b >> 2) & 1;
#pragma unroll
      for (int j = 0; j < 4; ++j) {
        const int d = c4 + j;
        const int idx = (d >> 3) * 4 + (d & 3);
        const int comp = (d >> 2) & 1;
        ((uint32_t*)&K2n[key_a][idx])[comp] = f2tf32(ka0[j]);
        ((uint32_t*)&K2n[key_b][idx])[comp] = f2tf32(kb0[j]);
        ((uint32_t*)&V2n[d][kidx_a])[kcomp_a] = f2tf32(va0[j]);
        ((uint32_t*)&V2n[d][kidx_b])[kcomp_b] = f2tf32(vb0[j]);
      }
    }
  }

  // ---- epilogue: divide by l, store to g_ao [b][s][h*64+d] ----
  const float il0 = 1.f / l0v;
  const float il1 = 1.f / l1v;
  float* aob = g_ao + ((size_t)(b * SEQ + q0)) * EMB + h * HD;
#pragma unroll
  for (int dt = 0; dt < 8; ++dt) {
    const int d0 = dt * 8 + qp * 2;
    float2 v0 = {o[dt][0] * il0, o[dt][1] * il0};
    float2 v1 = {o[dt][2] * il1, o[dt][3] * il1};
    *(float2*)(aob + (size_t)qrow * EMB + d0) = v0;
    *(float2*)(aob + (size_t)(qrow + 8) * EMB + d0) = v1;
  }
}

// ---------------------------------------------------------------------------
extern "C" void kernel_launch(void* const* d_in, const int* in_sizes, int n_in,
                              void* d_out, int out_size) {
  (void)in_sizes; (void)n_in; (void)out_size;
  const float* query = (const float*)d_in[0];
  // d_in[1]=key, d_in[2]=value: ignored by the reference module
  const float* Wqkv = (const float*)d_in[3];
  const float* bqkv = (const float*)d_in[4];
  const float* Wout = (const float*)d_in[5];
  const float* bout = (const float*)d_in[6];
  float* out = (float*)d_out;

  cudaFuncSetAttribute(gemm_mma_kernel<0>,
                       cudaFuncAttributeMaxDynamicSharedMemorySize,
                       GEMM_SMEM_BYTES);
  cudaFuncSetAttribute(gemm_mma_kernel<1>,
                       cudaFuncAttributeMaxDynamicSharedMemorySize,
                       GEMM_SMEM_BYTES);
  cudaFuncSetAttribute(flash_mma_kernel,
                       cudaFuncAttributeMaxDynamicSharedMemorySize,
                       ATTN_SMEM_BYTES);

  dim3 g1(24, 64);   // 3072/128 x 8192/128
  gemm_mma_kernel<0><<<g1, 256, GEMM_SMEM_BYTES>>>(query, Wqkv, bqkv, nullptr);

  dim3 g2(64, 16);   // (b*h) x (S/128)
  flash_mma_kernel<<<g2, 256, ATTN_SMEM_BYTES>>>();

  dim3 g3(8, 64);    // 1024/128 x 8192/128
  gemm_mma_kernel<1><<<g3, 256, GEMM_SMEM_BYTES>>>(nullptr, Wout, bout, out);
}